// round 6
// baseline (speedup 1.0000x reference)
#include <cuda_runtime.h>

// Demolition_Conv2d: grouped conv (16 groups of 1->32, 3x3, pad 1) + bias,
// per-(cin,cout) 5-bit quant-dequant (scale=15/9), sum over cin.
//
// R6: L1-wavefront fix. Prepass builds padded even-pair stream
//   Epad[bc][hp][i] = (x[2i-2], x[2i-1])  (zeros OOB), hp = xrow+1.
// Main: block = (b, coutgrp, 16-row band), 224 threads = 8 row-pairs x 28
// 4px tiles. Per cin: E tile staged to smem (coalesced LDG.128, double
// buffered, prefetch overlapped with compute); taps read as conflict-free
// LDS.128; odd pairs built with 1 mov each. FFMA2 everywhere, magic-RNE.

#define CIN   16
#define COUT  32
#define HH    112
#define WW    112
#define NB    8
#define NC    4
#define HP    114
#define PW    60      // padded pairs per row
#define BAND  16      // output rows per block
#define NT    224     // 8 row-pairs x 28 wtiles
#define SROWS 18      // staged padded rows per band (BAND+2)

typedef unsigned long long f2;

__device__ __align__(16) f2 g_E[NB * CIN * HP * PW];   // ~7.0 MB

__device__ __forceinline__ f2 pk2(float lo, float hi) {
    f2 r; asm("mov.b64 %0, {%1, %2};" : "=l"(r) : "f"(lo), "f"(hi)); return r;
}
__device__ __forceinline__ void fma2i(f2& acc, f2 a, f2 b) {
    asm("fma.rn.f32x2 %0, %1, %2, %0;" : "+l"(acc) : "l"(a), "l"(b));
}
__device__ __forceinline__ void add2i(f2& acc, f2 b) {
    asm("add.rn.f32x2 %0, %0, %1;" : "+l"(acc) : "l"(b));
}
__device__ __forceinline__ f2 mul2(f2 a, f2 b) {
    f2 d; asm("mul.rn.f32x2 %0, %1, %2;" : "=l"(d) : "l"(a), "l"(b)); return d;
}
// odd pair: (a.hi, b.lo)
__device__ __forceinline__ f2 comb(f2 a, f2 b) {
    f2 r;
    asm("{\n\t.reg .b32 al, ah, bl, bh;\n\t"
        "mov.b64 {al, ah}, %1;\n\t"
        "mov.b64 {bl, bh}, %2;\n\t"
        "mov.b64 %0, {ah, bl};\n\t}"
        : "=l"(r) : "l"(a), "l"(b));
    return r;
}

// ---------------- prepass: padded even-pair stream ----------------
__global__ __launch_bounds__(256)
void prepass_kernel(const float* __restrict__ x)
{
    int gid = blockIdx.x * 256 + threadIdx.x;   // [0, NB*CIN*HP*PW)
    int i  = gid % PW;
    int t  = gid / PW;
    int hp = t % HP;
    int bc = t / HP;
    int hrow = hp - 1;
    bool rv = (hrow >= 0) && (hrow < HH);
    const float* row = x + (bc * HH + hrow) * WW;
    int c0 = 2 * i - 2;
    int c1 = 2 * i - 1;
    float x0 = (rv && c0 >= 0 && c0 < WW) ? row[c0] : 0.0f;
    float x1 = (rv && c1 >= 0 && c1 < WW) ? row[c1] : 0.0f;
    g_E[gid] = pk2(x0, x1);
}

// ---------------- main kernel ----------------
__global__ __launch_bounds__(NT, 2)
void demolition_conv2d_kernel(const float* __restrict__ Wt,
                              const float* __restrict__ bias,
                              float* __restrict__ out)
{
    __shared__ __align__(16) f2 sE[2][SROWS * PW];      // 2 x 8640 B
    __shared__ __align__(16) f2 sW[CIN * NC * 10];      // 5120 B

    const float SCALEf = 15.0f / 9.0f;
    const float INVf   = 9.0f / 15.0f;
    const float MAGICf = 12582912.0f;   // 1.5 * 2^23

    // Grid: 448 blocks = 8 b x 8 grp x 7 bands.
    int bx   = blockIdx.x;
    int b    = bx / 56;
    int rem  = bx % 56;
    int grp  = rem / 7;
    int band = rem % 7;
    int h0   = band * BAND;
    int co_base = grp * NC;

    int tid = threadIdx.x;
    int rp  = tid / 28;          // row-pair 0..7
    int wt  = tid % 28;          // 4px tile 0..27

    // Stage weights (scaled, duplicated): [cin][lc][w0..w8,bias].
    for (int i = tid; i < CIN * NC * 10; i += NT) {
        int e   = i / 10;
        int k   = i % 10;
        int cin = e / NC;
        int lc  = e % NC;
        int co  = co_base + lc;
        float v = (k < 9) ? Wt[(cin * COUT + co) * 9 + k] : bias[cin * COUT + co];
        v *= SCALEf;
        sW[i] = pk2(v, v);
    }

    const f2 MAG2  = pk2(MAGICf,  MAGICf);
    const f2 NMAG2 = pk2(-MAGICf, -MAGICf);
    const f2 INV2  = pk2(INVf,    INVf);

    // E-stage addressing: 18 rows x 60 pairs = 540 ulonglong2 per cin.
    const int U2 = SROWS * PW / 2;          // 540
    int i0 = tid, i1 = tid + NT, i2 = tid + 2 * NT;   // i2 < 540 iff tid < 92

    // Prologue: stage cin 0 into buffer 0.
    {
        const ulonglong2* src = reinterpret_cast<const ulonglong2*>(
            g_E + ((long)(b * CIN + 0) * HP + h0) * PW);
        ulonglong2* dst = reinterpret_cast<ulonglong2*>(sE[0]);
        ulonglong2 v0 = src[i0];
        ulonglong2 v1 = src[i1];
        ulonglong2 v2 = (i2 < U2) ? src[i2] : make_ulonglong2(0, 0);
        dst[i0] = v0;
        dst[i1] = v1;
        if (i2 < U2) dst[i2] = v2;
    }
    __syncthreads();

    f2 acc[NC][2][2];
#pragma unroll
    for (int c = 0; c < NC; ++c)
#pragma unroll
        for (int r = 0; r < 2; ++r) { acc[c][r][0] = 0ULL; acc[c][r][1] = 0ULL; }

#pragma unroll 1
    for (int cin = 0; cin < CIN; ++cin) {
        // Prefetch next cin tile into registers (overlaps with compute).
        ulonglong2 v0, v1, v2;
        if (cin + 1 < CIN) {
            const ulonglong2* src = reinterpret_cast<const ulonglong2*>(
                g_E + ((long)(b * CIN + cin + 1) * HP + h0) * PW);
            v0 = src[i0];
            v1 = src[i1];
            v2 = (i2 < U2) ? src[i2] : make_ulonglong2(0, 0);
        }

        const f2* S = sE[cin & 1];

        // Load 4 padded rows x 4 pairs; build taps {o0,e0,o1,e1,o2} per row.
        f2 tp[4][5];
#pragma unroll
        for (int k = 0; k < 4; ++k) {
            const ulonglong2* rowp = reinterpret_cast<const ulonglong2*>(
                S + (rp * 2 + k) * PW + 2 * wt);
            ulonglong2 A = rowp[0];     // Epad[P], Epad[P+1]
            ulonglong2 B = rowp[1];     // Epad[P+2], Epad[P+3]
            tp[k][0] = comb(A.x, A.y);  // o0
            tp[k][1] = A.y;             // e0
            tp[k][2] = comb(A.y, B.x);  // o1
            tp[k][3] = B.x;             // e1
            tp[k][4] = comb(B.x, B.y);  // o2
        }

        const ulonglong2* wb =
            reinterpret_cast<const ulonglong2*>(&sW[cin * NC * 10]);

#pragma unroll
        for (int c = 0; c < NC; ++c) {
            ulonglong2 w01 = wb[c * 5 + 0];   // w0, w1
            ulonglong2 w23 = wb[c * 5 + 1];   // w2, w3
            ulonglong2 w45 = wb[c * 5 + 2];   // w4, w5
            ulonglong2 w67 = wb[c * 5 + 3];   // w6, w7
            ulonglong2 w8b = wb[c * 5 + 4];   // w8, bias

#pragma unroll
            for (int r = 0; r < 2; ++r) {
                f2 y0 = w8b.y;
                f2 y1 = w8b.y;
                // tap-row 0 -> padded row r
                fma2i(y0, tp[r][0], w01.x);  fma2i(y1, tp[r][2], w01.x);
                fma2i(y0, tp[r][1], w01.y);  fma2i(y1, tp[r][3], w01.y);
                fma2i(y0, tp[r][2], w23.x);  fma2i(y1, tp[r][4], w23.x);
                // tap-row 1 -> padded row r+1
                fma2i(y0, tp[r+1][0], w23.y);  fma2i(y1, tp[r+1][2], w23.y);
                fma2i(y0, tp[r+1][1], w45.x);  fma2i(y1, tp[r+1][3], w45.x);
                fma2i(y0, tp[r+1][2], w45.y);  fma2i(y1, tp[r+1][4], w45.y);
                // tap-row 2 -> padded row r+2
                fma2i(y0, tp[r+2][0], w67.x);  fma2i(y1, tp[r+2][2], w67.x);
                fma2i(y0, tp[r+2][1], w67.y);  fma2i(y1, tp[r+2][3], w67.y);
                fma2i(y0, tp[r+2][2], w8b.x);  fma2i(y1, tp[r+2][4], w8b.x);

                add2i(y0, MAG2);  add2i(y0, NMAG2);   // RNE -> integer
                add2i(y1, MAG2);  add2i(y1, NMAG2);
                add2i(acc[c][r][0], y0);
                add2i(acc[c][r][1], y1);
            }
        }

        // Write prefetched tile, then sync for next iteration.
        if (cin + 1 < CIN) {
            ulonglong2* dst = reinterpret_cast<ulonglong2*>(sE[(cin + 1) & 1]);
            dst[i0] = v0;
            dst[i1] = v1;
            if (i2 < U2) dst[i2] = v2;
        }
        __syncthreads();
    }

    // Store: per (cout, row) one 16B store of 4 pixels.
#pragma unroll
    for (int c = 0; c < NC; ++c) {
        int co = co_base + c;
#pragma unroll
        for (int r = 0; r < 2; ++r) {
            int h = h0 + rp * 2 + r;
            float* ob = out + ((long)(b * COUT + co) * HH + h) * WW + wt * 4;
            ulonglong2 v;
            v.x = mul2(acc[c][r][0], INV2);
            v.y = mul2(acc[c][r][1], INV2);
            *reinterpret_cast<ulonglong2*>(ob) = v;
        }
    }
}

extern "C" void kernel_launch(void* const* d_in, const int* in_sizes, int n_in,
                              void* d_out, int out_size)
{
    const float* x    = (const float*)d_in[0];   // [8,16,112,112]
    const float* Wt   = (const float*)d_in[1];   // [16,32,1,3,3]
    const float* bias = (const float*)d_in[2];   // [16,32]
    float* out        = (float*)d_out;           // [8,32,112,112]

    // NB*CIN*HP*PW = 875520 = 3420 * 256 exactly.
    prepass_kernel<<<3420, 256>>>(x);
    demolition_conv2d_kernel<<<448, NT>>>(Wt, bias, out);
}

// round 7
// speedup vs baseline: 1.0766x; 1.0766x over previous
#include <cuda_runtime.h>

// Demolition_Conv2d: grouped conv (16 groups of 1->32, 3x3, pad 1) + bias,
// per-(cin,cout) 5-bit quant-dequant (scale=15/9), sum over cin.
//
// R7: pack CIN-PAIRS into f32x2 lanes (not column pairs). Prepass builds
// zero-padded packed planes Xp[b][cp][hp][wp] = (x[2cp],x[2cp+1]) so every
// conv tap is a direct 8B load -- no pair-construction MOVs, no boundary
// selects. Weights packed (w[2cp]*s, w[2cp+1]*s). Per-lane magic-RNE round,
// integer-valued per-lane accumulation, final lane sum * (1/s).

#define CIN   16
#define COUT  32
#define HH    112
#define WW    112
#define NB    8
#define NCP   8      // cin pairs
#define HP    114    // padded height
#define WP    114    // padded width
#define NC    2      // couts per thread

typedef unsigned long long f2;

__device__ __align__(16) f2 g_X[NB * NCP * HP * WP];   // ~6.65 MB packed planes

__device__ __forceinline__ f2 pk2(float lo, float hi) {
    f2 r; asm("mov.b64 %0, {%1, %2};" : "=l"(r) : "f"(lo), "f"(hi)); return r;
}
__device__ __forceinline__ void fma2i(f2& acc, f2 a, f2 b) {
    asm("fma.rn.f32x2 %0, %1, %2, %0;" : "+l"(acc) : "l"(a), "l"(b));
}
__device__ __forceinline__ void add2i(f2& acc, f2 b) {
    asm("add.rn.f32x2 %0, %0, %1;" : "+l"(acc) : "l"(b));
}
__device__ __forceinline__ float lanesum(f2 a) {
    float lo, hi;
    asm("mov.b64 {%0, %1}, %2;" : "=f"(lo), "=f"(hi) : "l"(a));
    return lo + hi;
}

// ---------------- prepass: padded cin-pair planes ----------------
__global__ __launch_bounds__(256)
void prepass_kernel(const float* __restrict__ x)
{
    int gid = blockIdx.x * 256 + threadIdx.x;    // [0, NB*NCP*HP*WP)
    int wp = gid % WP;
    int t  = gid / WP;
    int hp = t % HP;
    int t2 = t / HP;
    int cp = t2 % NCP;
    int b  = t2 / NCP;

    int h = hp - 1;
    int w = wp - 1;
    bool v = (h >= 0) && (h < HH) && (w >= 0) && (w < WW);

    const float* p0 = x + (((b * CIN + 2 * cp)     * HH + h) * WW) + w;
    const float* p1 = x + (((b * CIN + 2 * cp + 1) * HH + h) * WW) + w;
    float a = v ? *p0 : 0.0f;
    float c = v ? *p1 : 0.0f;
    g_X[gid] = pk2(a, c);
}

// ---------------- main kernel ----------------
__global__ __launch_bounds__(128, 5)
void demolition_conv2d_kernel(const float* __restrict__ Wt,
                              const float* __restrict__ bias,
                              float* __restrict__ out)
{
    // This block's 2 couts: [cp][lc][w0..w8, bias], lanes = (cin 2cp, 2cp+1),
    // pre-scaled by SCALE.
    __shared__ __align__(16) f2 sW[NCP * NC * 10];   // 1280 B

    const float SCALEf = 15.0f / 9.0f;
    const float INVf   = 9.0f / 15.0f;
    const float MAGICf = 12582912.0f;   // 1.5 * 2^23

    // g in [0, 401408). 25088 4-px tiles; cout group (16 of them) uniform
    // per block: 25088 = 196 * 128.
    int g = blockIdx.x * 128 + threadIdx.x;
    int grp = g / 25088;                 // 0..15
    int t  = g % 25088;
    int wt = t % 28;                     // 4-px tile in row
    int t1 = t / 28;
    int h  = t1 % HH;
    int b  = t1 / HH;
    int w0 = wt * 4;
    int co_base = grp * NC;

    for (int i = threadIdx.x; i < NCP * NC * 10; i += 128) {
        int e  = i / 10;
        int k  = i % 10;
        int cp = e / NC;
        int lc = e % NC;
        int co = co_base + lc;
        float v0, v1;
        if (k < 9) {
            v0 = Wt[((2 * cp)     * COUT + co) * 9 + k];
            v1 = Wt[((2 * cp + 1) * COUT + co) * 9 + k];
        } else {
            v0 = bias[(2 * cp)     * COUT + co];
            v1 = bias[(2 * cp + 1) * COUT + co];
        }
        sW[i] = pk2(v0 * SCALEf, v1 * SCALEf);
    }
    __syncthreads();

    const f2 MAG2  = pk2(MAGICf,  MAGICf);
    const f2 NMAG2 = pk2(-MAGICf, -MAGICf);

    f2 acc[NC][4];
#pragma unroll
    for (int c = 0; c < NC; ++c)
#pragma unroll
        for (int j = 0; j < 4; ++j) acc[c][j] = 0ULL;

#pragma unroll 1
    for (int cp = 0; cp < NCP; ++cp) {
        // Taps: 3 padded rows (hp = h..h+2), 6 f2 each (wp = w0..w0+5).
        const f2* base = g_X + ((long)(b * NCP + cp) * HP + h) * WP + w0;

        f2 tp[3][6];
#pragma unroll
        for (int r = 0; r < 3; ++r) {
            const ulonglong2* rp = reinterpret_cast<const ulonglong2*>(base + r * WP);
            ulonglong2 A = rp[0];
            ulonglong2 B = rp[1];
            ulonglong2 C = rp[2];
            tp[r][0] = A.x; tp[r][1] = A.y;
            tp[r][2] = B.x; tp[r][3] = B.y;
            tp[r][4] = C.x; tp[r][5] = C.y;
        }

        const ulonglong2* wb =
            reinterpret_cast<const ulonglong2*>(&sW[cp * NC * 10]);

#pragma unroll
        for (int c = 0; c < NC; ++c) {
            ulonglong2 w01 = wb[c * 5 + 0];   // w0, w1
            ulonglong2 w23 = wb[c * 5 + 1];   // w2, w3
            ulonglong2 w45 = wb[c * 5 + 2];   // w4, w5
            ulonglong2 w67 = wb[c * 5 + 3];   // w6, w7
            ulonglong2 w8b = wb[c * 5 + 4];   // w8, bias

#pragma unroll
            for (int j = 0; j < 4; ++j) {
                f2 y = w8b.y;
                fma2i(y, tp[0][j],     w01.x);
                fma2i(y, tp[0][j + 1], w01.y);
                fma2i(y, tp[0][j + 2], w23.x);
                fma2i(y, tp[1][j],     w23.y);
                fma2i(y, tp[1][j + 1], w45.x);
                fma2i(y, tp[1][j + 2], w45.y);
                fma2i(y, tp[2][j],     w67.x);
                fma2i(y, tp[2][j + 1], w67.y);
                fma2i(y, tp[2][j + 2], w8b.x);

                add2i(y, MAG2);          // per-lane RNE -> integer
                add2i(y, NMAG2);
                add2i(acc[c][j], y);     // exact integer-valued sums
            }
        }
    }

    // Final: sum the two cin lanes, scale by 1/SCALE, store 4 px per cout.
#pragma unroll
    for (int c = 0; c < NC; ++c) {
        int co = co_base + c;
        float4 v;
        v.x = lanesum(acc[c][0]) * INVf;
        v.y = lanesum(acc[c][1]) * INVf;
        v.z = lanesum(acc[c][2]) * INVf;
        v.w = lanesum(acc[c][3]) * INVf;
        float* ob = out + ((long)(b * COUT + co) * HH + h) * WW + w0;
        *reinterpret_cast<float4*>(ob) = v;
    }
}

extern "C" void kernel_launch(void* const* d_in, const int* in_sizes, int n_in,
                              void* d_out, int out_size)
{
    const float* x    = (const float*)d_in[0];   // [8,16,112,112]
    const float* Wt   = (const float*)d_in[1];   // [16,32,1,3,3]
    const float* bias = (const float*)d_in[2];   // [16,32]
    float* out        = (float*)d_out;           // [8,32,112,112]

    // NB*NCP*HP*WP = 831744 = 3249 * 256 exactly.
    prepass_kernel<<<3249, 256>>>(x);
    // 401408 threads = 3136 blocks * 128.
    demolition_conv2d_kernel<<<3136, 128>>>(Wt, bias, out);
}